// round 16
// baseline (speedup 1.0000x reference)
#include <cuda_runtime.h>
#include <cuda_fp16.h>
#include <cstdint>
#include <math.h>

#define T_ROWS 8192
#define D_DIM  4096
#define E_DIM  64
#define TE     (T_ROWS * E_DIM)     // 524288

#define KC        64                 // K per chunk
#define NCH       32                 // chunks per CTA (split-K: 2048 per half)
#define BROW      144                // B row stride bytes (64 fp16 = 128B + pad)
#define BTILE     (64 * BROW)        // 9216 B per split per chunk
#define BSTAGE    (2 * BTILE)        // 18432 B per stage (2 splits)
#define SMEM_DYN  (3 * BSTAGE + 256)

#define BSCALE    4096.0f            // 2^12, exact
#define BSCALE_INV (1.0f / 4096.0f)

// W pre-scaled by 2^12 and split into 2 fp16 tiles: [split][chunk 64][e 64][BROW]
__device__ __align__(16) unsigned char g_Bb[2 * 64 * BTILE];
// split-K partial for K-half 1
__device__ float g_part[TE];

// ---------------------------------------------------------------------------
// helpers
// ---------------------------------------------------------------------------
__device__ __forceinline__ unsigned sptr(const void* p) {
    return (unsigned)__cvta_generic_to_shared(p);
}
__device__ __forceinline__ uint32_t packh2(__half lo, __half hi) {
    __half2 v = __halves2half2(lo, hi);
    return *reinterpret_cast<uint32_t*>(&v);
}
// 2-way fp16 split: a ~= h + l (residual error ~2^-22 |a|)
__device__ __forceinline__ void split2(float a, __half& h, __half& l) {
    h = __float2half_rn(a);
    float r = a - __half2float(h);
    l = __float2half_rn(r);
}
// split a float2 (consecutive k) into hi/lo packed fp16x2
__device__ __forceinline__ void split_pack2(float2 f, uint32_t& ph, uint32_t& pl) {
    __half hx, lx, hy, ly;
    split2(f.x, hx, lx);
    split2(f.y, hy, ly);
    ph = packh2(hx, hy);
    pl = packh2(lx, ly);
}
// m16n8k16 fp16 MMA, fp32 accumulate (baseline PTX, sm_80+)
__device__ __forceinline__ void mma16816(float4& c, const uint32_t a[4],
                                         uint32_t b0, uint32_t b1) {
    asm volatile(
        "mma.sync.aligned.m16n8k16.row.col.f32.f16.f16.f32 "
        "{%0,%1,%2,%3}, {%4,%5,%6,%7}, {%8,%9}, {%0,%1,%2,%3};"
        : "+f"(c.x), "+f"(c.y), "+f"(c.z), "+f"(c.w)
        : "r"(a[0]), "r"(a[1]), "r"(a[2]), "r"(a[3]), "r"(b0), "r"(b1));
}
__device__ __forceinline__ uint32_t lds32(uint32_t addr) {
    uint32_t v;
    asm volatile("ld.shared.b32 %0, [%1];" : "=r"(v) : "r"(addr));
    return v;
}

// ---------------------------------------------------------------------------
// Kernel 0: W[E][D] fp32 -> x4096 -> 2 fp16 chunk tiles, row stride 144 B
// ---------------------------------------------------------------------------
__global__ void k_prep_b(const float* __restrict__ W) {
    int task = blockIdx.x * 256 + threadIdx.x;      // 65536 = E * D/4
    int e = task >> 10;
    int k = (task & 1023) * 4;
    float4 w = *(const float4*)(W + (size_t)e * D_DIM + k);
    w.x *= BSCALE; w.y *= BSCALE; w.z *= BSCALE; w.w *= BSCALE;
    int chunk = k >> 6;
    int kk = k & 63;
    __half h[4], l[4];
    split2(w.x, h[0], l[0]);
    split2(w.y, h[1], l[1]);
    split2(w.z, h[2], l[2]);
    split2(w.w, h[3], l[3]);
    size_t base = (size_t)e * BROW + (size_t)kk * 2;
    *(uint2*)(g_Bb + (size_t)chunk * BTILE + base) =
        make_uint2(packh2(h[0], h[1]), packh2(h[2], h[3]));
    *(uint2*)(g_Bb + (size_t)(64 + chunk) * BTILE + base) =
        make_uint2(packh2(l[0], l[1]), packh2(l[2], l[3]));
}

// ---------------------------------------------------------------------------
// Kernel 1: HMMA GEMM. 128 CTAs = 64 m-tiles x 2 k-halves, 512 threads.
//   16 warps = 8 m-subtiles x 2 n-halves; warp -> 16 rows x 32 cols
//   (4 n-tiles). 4 warps/SMSP for latency hiding of split/LDS chains.
//   fp16 2-split, 3 products (hh, hl, lh); drain to fp32 master every
//   2 chunks. kh=0 writes logits(+bias), kh=1 writes g_part; router sums.
// ---------------------------------------------------------------------------
__global__ __launch_bounds__(512, 1)
void k_gemm_hmma(const float* __restrict__ h, const float* __restrict__ bias,
                 float* __restrict__ logits) {
    extern __shared__ __align__(16) unsigned char smem_raw[];
    const uint32_t sB = sptr(smem_raw);

    const int tid = threadIdx.x;
    const int w = tid >> 5;
    const int lane = tid & 31;
    const int mw = w >> 1;             // m-subtile 0..7
    const int nh = w & 1;              // n-half 0..1
    const int mt = blockIdx.x >> 1;
    const int kh = blockIdx.x & 1;
    const int row0 = mt * 128;

    const int lr = lane >> 2;          // row-in-group 0..7
    const int lq = lane & 3;           // quad col id

    const float* hA = h + (size_t)(row0 + mw * 16 + lr) * D_DIM + kh * 2048 + lq * 2;

#define PF_B(C, S) do {                                                       \
    size_t _srcb = (size_t)(kh * 32 + (C)) * BTILE;                           \
    _Pragma("unroll")                                                         \
    for (int _j = 0; _j < 3; _j++) {                                          \
        int _i = tid + 512 * _j;                                              \
        if (_i < BSTAGE / 16) {                                               \
            int _sp = _i / (BTILE / 16);                                      \
            int _wo = _i % (BTILE / 16);                                      \
            unsigned _d = sB + (S) * BSTAGE + _sp * BTILE + _wo * 16;         \
            const unsigned char* _s =                                         \
                g_Bb + (size_t)_sp * 64 * BTILE + _srcb + (size_t)_wo * 16;   \
            asm volatile("cp.async.ca.shared.global [%0], [%1], 16;"          \
                         :: "r"(_d), "l"(_s));                                \
        }                                                                     \
    }                                                                         \
    asm volatile("cp.async.commit_group;");                                   \
} while (0)

    float4 acc[4];      // HMMA window accumulators (reset every 2 chunks)
    float4 master[4];   // fp32 RN master sums
#pragma unroll
    for (int j = 0; j < 4; j++) {
        acc[j]    = make_float4(0.f, 0.f, 0.f, 0.f);
        master[j] = make_float4(0.f, 0.f, 0.f, 0.f);
    }

    PF_B(0, 0);
    PF_B(1, 1);

    // A regs for chunk 0
    float2 rA[16];
#pragma unroll
    for (int s = 0; s < 4; s++) {
        const float* p = hA + s * 16;
        rA[s * 4 + 0] = *(const float2*)(p);
        rA[s * 4 + 1] = *(const float2*)(p + 8 * D_DIM);
        rA[s * 4 + 2] = *(const float2*)(p + 8);
        rA[s * 4 + 3] = *(const float2*)(p + 8 * D_DIM + 8);
    }

    for (int c = 0; c < NCH; c++) {
        if (c < NCH - 1) asm volatile("cp.async.wait_group 1;");
        else             asm volatile("cp.async.wait_group 0;");
        __syncthreads();
        if (c + 2 < NCH) PF_B(c + 2, (c + 2) % 3);

        // prefetch next chunk's A
        float2 rAn[16];
        if (c + 1 < NCH) {
            const float* pc = hA + (c + 1) * KC;
#pragma unroll
            for (int s = 0; s < 4; s++) {
                const float* p = pc + s * 16;
                rAn[s * 4 + 0] = *(const float2*)(p);
                rAn[s * 4 + 1] = *(const float2*)(p + 8 * D_DIM);
                rAn[s * 4 + 2] = *(const float2*)(p + 8);
                rAn[s * 4 + 3] = *(const float2*)(p + 8 * D_DIM + 8);
            }
        }

        const uint32_t stg = sB + (c % 3) * BSTAGE;
        const uint32_t bbase = stg + (uint32_t)lr * BROW + (uint32_t)lq * 4 +
                               (uint32_t)nh * (4 * 8 * BROW);

#pragma unroll
        for (int s = 0; s < 4; s++) {
            uint32_t ah[4], al[4];
            split_pack2(rA[s * 4 + 0], ah[0], al[0]);
            split_pack2(rA[s * 4 + 1], ah[1], al[1]);
            split_pack2(rA[s * 4 + 2], ah[2], al[2]);
            split_pack2(rA[s * 4 + 3], ah[3], al[3]);

            const uint32_t bs = bbase + (uint32_t)s * 32;
#pragma unroll
            for (int j = 0; j < 4; j++) {
                uint32_t ro = bs + (uint32_t)j * (8 * BROW);
                uint32_t bh0 = lds32(ro),         bh1 = lds32(ro + 16);
                uint32_t bl0 = lds32(ro + BTILE), bl1 = lds32(ro + BTILE + 16);
                mma16816(acc[j], ah, bh0, bh1);   // hh
                mma16816(acc[j], ah, bl0, bl1);   // hl
                mma16816(acc[j], al, bh0, bh1);   // lh
            }
        }

        // drain HMMA window into fp32 master every 2 chunks
        if ((c & 1) == 1) {
#pragma unroll
            for (int j = 0; j < 4; j++) {
                master[j].x += acc[j].x;
                master[j].y += acc[j].y;
                master[j].z += acc[j].z;
                master[j].w += acc[j].w;
                acc[j] = make_float4(0.f, 0.f, 0.f, 0.f);
            }
        }

#pragma unroll
        for (int i = 0; i < 16; i++) rA[i] = rAn[i];
    }

    // epilogue: undo B scale (exact 2^-12), add bias on kh=0
    float* dst = (kh == 0) ? logits : g_part;
    const int rg = row0 + mw * 16 + lr;
#pragma unroll
    for (int j = 0; j < 4; j++) {
        int col = (nh * 4 + j) * 8 + lq * 2;
        float b0 = (kh == 0) ? __ldg(bias + col)     : 0.f;
        float b1 = (kh == 0) ? __ldg(bias + col + 1) : 0.f;
        *(float2*)(dst + (size_t)rg * E_DIM + col) =
            make_float2(master[j].x * BSCALE_INV + b0,
                        master[j].y * BSCALE_INV + b1);
        *(float2*)(dst + (size_t)(rg + 8) * E_DIM + col) =
            make_float2(master[j].z * BSCALE_INV + b0,
                        master[j].w * BSCALE_INV + b1);
    }
#undef PF_B
}

// ---------------------------------------------------------------------------
// JAX threefry2x32, key = jax.random.key(42) -> (0, 42)
// ---------------------------------------------------------------------------
__device__ __forceinline__ uint32_t rotl32(uint32_t x, int r) {
    return __funnelshift_l(x, x, r);
}
__device__ __forceinline__ void threefry_42(uint32_t c0, uint32_t c1,
                                            uint32_t& o0, uint32_t& o1) {
    const uint32_t ks0 = 0u, ks1 = 42u, ks2 = 0x1BD11BDAu ^ 0u ^ 42u;
    uint32_t x0 = c0 + ks0, x1 = c1 + ks1;
#define TF_R(r) { x0 += x1; x1 = rotl32(x1, (r)); x1 ^= x0; }
    TF_R(13) TF_R(15) TF_R(26) TF_R(6);   x0 += ks1; x1 += ks2 + 1u;
    TF_R(17) TF_R(29) TF_R(16) TF_R(24);  x0 += ks2; x1 += ks0 + 2u;
    TF_R(13) TF_R(15) TF_R(26) TF_R(6);   x0 += ks0; x1 += ks1 + 3u;
    TF_R(17) TF_R(29) TF_R(16) TF_R(24);  x0 += ks1; x1 += ks2 + 4u;
    TF_R(13) TF_R(15) TF_R(26) TF_R(6);   x0 += ks2; x1 += ks0 + 5u;
#undef TF_R
    o0 = x0; o1 = x1;
}
// partitionable path: counter lanes (0, i), bits = o0 ^ o1
__device__ __forceinline__ float gumbel_at(uint32_t i) {
    uint32_t o0, o1;
    threefry_42(0u, i, o0, o1);
    uint32_t bits = o0 ^ o1;
    float f = __uint_as_float((bits >> 9) | 0x3F800000u) - 1.0f;
    const float minv  = (float)1e-6;
    const float maxv  = (float)(1.0 - 1e-6);
    const float scale = maxv - minv;
    float u = __fadd_rn(__fmul_rn(f, scale), minv);
    u = fmaxf(minv, u);
    return -logf(-logf(u));
}

// ---------------------------------------------------------------------------
// Kernel 2: sum split-K partials -> final logits; softmax + Gumbel top-k.
// One warp per row.
// ---------------------------------------------------------------------------
__global__ __launch_bounds__(256)
void k_router(float* __restrict__ logits, const int* __restrict__ kin,
              float* __restrict__ mask, float* __restrict__ weight) {
    const int gw = (int)((blockIdx.x * blockDim.x + threadIdx.x) >> 5);
    const int lane = threadIdx.x & 31;
    if (gw >= T_ROWS) return;

    int K = 8;
    if (kin) { K = *kin; if (K < 0) K = 0; if (K > E_DIM) K = E_DIM; }

    const size_t i0 = (size_t)gw * E_DIM + lane;
    const size_t i1 = i0 + 32;
    float l0 = logits[i0] + g_part[i0];
    float l1 = logits[i1] + g_part[i1];
    logits[i0] = l0;          // final logits output
    logits[i1] = l1;

    float mx = fmaxf(l0, l1);
#pragma unroll
    for (int o = 16; o; o >>= 1) mx = fmaxf(mx, __shfl_xor_sync(0xffffffffu, mx, o));
    float p0 = expf(l0 - mx), p1 = expf(l1 - mx);
    float s = p0 + p1;
#pragma unroll
    for (int o = 16; o; o >>= 1) s += __shfl_xor_sync(0xffffffffu, s, o);
    weight[i0] = p0 / s;
    weight[i1] = p1 / s;

    const uint32_t base = (uint32_t)gw * 64u;
    float s0 = l0 + gumbel_at(base + (uint32_t)lane);
    float s1 = l1 + gumbel_at(base + (uint32_t)lane + 32u);

    const float NEG_INF = __int_as_float(0xff800000);
    const int e0 = lane, e1 = lane + 32;
    float m0 = 0.0f, m1 = 0.0f;

    for (int kk = 0; kk < K; kk++) {
        float v = s0; int ii = e0;
        if (s1 > v) { v = s1; ii = e1; }
#pragma unroll
        for (int o = 16; o; o >>= 1) {
            float ov = __shfl_xor_sync(0xffffffffu, v, o);
            int   oi = __shfl_xor_sync(0xffffffffu, ii, o);
            if (ov > v || (ov == v && oi < ii)) { v = ov; ii = oi; }
        }
        if (ii == e0)      { m0 = 1.0f; s0 = NEG_INF; }
        else if (ii == e1) { m1 = 1.0f; s1 = NEG_INF; }
    }

    mask[i0] = m0;
    mask[i1] = m1;
}

// ---------------------------------------------------------------------------
// launch: prep W splits -> HMMA split-K GEMM -> router (sum + topk)
// out layout (f32): [ mask (T*E) | weight (T*E) | logits (T*E) ]
// ---------------------------------------------------------------------------
extern "C" void kernel_launch(void* const* d_in, const int* in_sizes, int n_in,
                              void* d_out, int out_size) {
    const float* h    = (const float*)d_in[0];
    const float* W    = (const float*)d_in[1];
    const float* bias = (const float*)d_in[2];
    const int*   kin  = (n_in > 3 && in_sizes[3] == 1) ? (const int*)d_in[3] : nullptr;

    float* out    = (float*)d_out;
    float* mask   = out;
    float* weight = out + TE;
    float* logits = out + 2 * TE;

    cudaFuncSetAttribute(k_gemm_hmma,
                         cudaFuncAttributeMaxDynamicSharedMemorySize, SMEM_DYN);

    k_prep_b<<<256, 256>>>(W);
    k_gemm_hmma<<<128, 512, SMEM_DYN>>>(h, bias, logits);
    k_router<<<(T_ROWS * 32) / 256, 256>>>(logits, kin, mask, weight);
}